// round 10
// baseline (speedup 1.0000x reference)
#include <cuda_runtime.h>
#include <math.h>
#include <stdint.h>

// ---------------- problem constants ----------------
#define Bb 64
#define Nn 300
#define Cc 256
#define Hh 8
#define HD 32
#define BH (Bb*Hh)          // 512
#define ROWS (Bb*Nn)        // 19200
#define QR 8                // queries per warp (register-blocked)
#define AW 8                // warps in attention CTA (2 CTAs/SM)

// ---------------- scratch (device globals; no runtime alloc) ----------------
__device__ float g_q[BH * Nn * HD];     // [b,h,n,d]
__device__ float g_k[BH * Nn * HD];
__device__ float g_v[BH * Nn * HD];
__device__ float g_posmx[Hh * Nn];      // per-(h,n) positional logit max
__device__ float g_posinv[Hh * Nn];     // g(h) / sum(exp(logit - max))
__device__ float g_oh[ROWS * Cc];       // attention output, [b,n,h*32+d]

// ---------------- packed f32x2 helpers ----------------
__device__ __forceinline__ unsigned long long pk2(float x, float y) {
    unsigned long long r;
    asm("mov.b64 %0, {%1,%2};" : "=l"(r)
        : "r"(__float_as_uint(x)), "r"(__float_as_uint(y)));
    return r;
}
__device__ __forceinline__ void fma2(unsigned long long& d,
                                     unsigned long long a, unsigned long long b) {
    asm("fma.rn.f32x2 %0, %1, %2, %0;" : "+l"(d) : "l"(a), "l"(b));
}
__device__ __forceinline__ void upk2(float& lo, float& hi, unsigned long long v) {
    uint32_t l, h;
    asm("mov.b64 {%0,%1}, %2;" : "=r"(l), "=r"(h) : "l"(v));
    lo = __uint_as_float(l); hi = __uint_as_float(h);
}

// =====================================================================
// positional softmax stats: logit[h][n][m] = w0*d + w2*d^2 + b, d = m-n.
// =====================================================================
__global__ void pos_kernel(const float* __restrict__ Wpos,
                           const float* __restrict__ bpos,
                           const float* __restrict__ gating)
{
    int row  = blockIdx.x * 4 + (threadIdx.x >> 5);   // h*300 + n
    int lane = threadIdx.x & 31;
    if (row >= Hh * Nn) return;
    int h = row / Nn, n = row % Nn;
    float w0 = Wpos[h*3+0], w2 = Wpos[h*3+2], b = bpos[h];

    float s[10], mx = -1e30f;
    #pragma unroll
    for (int t = 0; t < 10; t++) {
        int m = t*32 + lane;
        float v = -1e30f;
        if (m < Nn) { float d = (float)(m - n); v = fmaf(w2*d, d, fmaf(w0, d, b)); }
        s[t] = v; mx = fmaxf(mx, v);
    }
    #pragma unroll
    for (int o = 16; o; o >>= 1) mx = fmaxf(mx, __shfl_xor_sync(0xffffffffu, mx, o));
    float esum = 0.f;
    #pragma unroll
    for (int t = 0; t < 10; t++) esum += __expf(s[t] - mx);
    #pragma unroll
    for (int o = 16; o; o >>= 1) esum += __shfl_xor_sync(0xffffffffu, esum, o);
    if (lane == 0) {
        float g = 1.0f / (1.0f + __expf(-gating[h]));
        g_posmx[row]  = mx;
        g_posinv[row] = g / esum;
    }
}

// =====================================================================
// GEMM (R6/R9 version, measured 53us proj): out = A[M,256] @ W[N,256]^T
// =====================================================================
#define KT 16
__global__ __launch_bounds__(256, 2)
void gemm_kernel(const float* __restrict__ A,
                 const float* __restrict__ W0,
                 const float* __restrict__ W1,
                 const float* __restrict__ bias,
                 float* __restrict__ out,
                 int mode)
{
    __shared__ __align__(16) float As[2][KT][132];
    __shared__ __align__(16) float Bs[2][KT][132];

    int tid  = threadIdx.x;
    int row0 = blockIdx.y * 128;
    int col0 = blockIdx.x * 128;
    int tx = tid & 15, ty = tid >> 4;

    const float* Ap = (mode == 0) ? A : g_oh;

    int lr = tid >> 1;
    int lk = (tid & 1) * 8;
    const float* arow = Ap + (size_t)(row0 + lr) * 256 + lk;
    int c = col0 + lr;
    const float* wrow;
    if (mode == 0) wrow = (c < 512) ? (W0 + (size_t)c * 256 + lk)
                                    : (W1 + (size_t)(c - 512) * 256 + lk);
    else           wrow = W0 + (size_t)c * 256 + lk;

    unsigned long long acc2[8][4];
    #pragma unroll
    for (int i = 0; i < 8; i++)
        #pragma unroll
        for (int jp = 0; jp < 4; jp++) acc2[i][jp] = 0ULL;

    float4 ra0, ra1, rb0, rb1;
    ra0 = *(const float4*)(arow + 0);
    ra1 = *(const float4*)(arow + 4);
    rb0 = *(const float4*)(wrow + 0);
    rb1 = *(const float4*)(wrow + 4);
    int buf = 0;
    {
        As[0][lk+0][lr]=ra0.x; As[0][lk+1][lr]=ra0.y; As[0][lk+2][lr]=ra0.z; As[0][lk+3][lr]=ra0.w;
        As[0][lk+4][lr]=ra1.x; As[0][lk+5][lr]=ra1.y; As[0][lk+6][lr]=ra1.z; As[0][lk+7][lr]=ra1.w;
        Bs[0][lk+0][lr]=rb0.x; Bs[0][lk+1][lr]=rb0.y; Bs[0][lk+2][lr]=rb0.z; Bs[0][lk+3][lr]=rb0.w;
        Bs[0][lk+4][lr]=rb1.x; Bs[0][lk+5][lr]=rb1.y; Bs[0][lk+6][lr]=rb1.z; Bs[0][lk+7][lr]=rb1.w;
    }
    __syncthreads();

    for (int k0 = 0; k0 < 256; k0 += KT) {
        bool has_next = (k0 + KT) < 256;
        if (has_next) {
            ra0 = *(const float4*)(arow + k0 + KT + 0);
            ra1 = *(const float4*)(arow + k0 + KT + 4);
            rb0 = *(const float4*)(wrow + k0 + KT + 0);
            rb1 = *(const float4*)(wrow + k0 + KT + 4);
        }
        #pragma unroll
        for (int kk = 0; kk < KT; kk++) {
            float4 a0 = *(const float4*)&As[buf][kk][ty*4];
            float4 a1 = *(const float4*)&As[buf][kk][64 + ty*4];
            ulonglong2 bb0 = *(const ulonglong2*)&Bs[buf][kk][tx*4];
            ulonglong2 bb1 = *(const ulonglong2*)&Bs[buf][kk][64 + tx*4];
            unsigned long long bp[4] = {bb0.x, bb0.y, bb1.x, bb1.y};
            float a[8] = {a0.x,a0.y,a0.z,a0.w, a1.x,a1.y,a1.z,a1.w};
            #pragma unroll
            for (int i = 0; i < 8; i++) {
                unsigned long long ap = pk2(a[i], a[i]);
                #pragma unroll
                for (int jp = 0; jp < 4; jp++)
                    fma2(acc2[i][jp], ap, bp[jp]);
            }
        }
        if (has_next) {
            int nb = buf ^ 1;
            As[nb][lk+0][lr]=ra0.x; As[nb][lk+1][lr]=ra0.y; As[nb][lk+2][lr]=ra0.z; As[nb][lk+3][lr]=ra0.w;
            As[nb][lk+4][lr]=ra1.x; As[nb][lk+5][lr]=ra1.y; As[nb][lk+6][lr]=ra1.z; As[nb][lk+7][lr]=ra1.w;
            Bs[nb][lk+0][lr]=rb0.x; Bs[nb][lk+1][lr]=rb0.y; Bs[nb][lk+2][lr]=rb0.z; Bs[nb][lk+3][lr]=rb0.w;
            Bs[nb][lk+4][lr]=rb1.x; Bs[nb][lk+5][lr]=rb1.y; Bs[nb][lk+6][lr]=rb1.z; Bs[nb][lk+7][lr]=rb1.w;
            __syncthreads();
            buf = nb;
        }
    }

    #pragma unroll
    for (int i = 0; i < 8; i++) {
        int r = row0 + ((i < 4) ? (ty*4 + i) : (64 + ty*4 + i - 4));
        int bidx = r / Nn, n = r % Nn;
        #pragma unroll
        for (int jp = 0; jp < 4; jp++) {
            int col = col0 + ((jp < 2) ? (tx*4 + jp*2) : (64 + tx*4 + (jp-2)*2));
            float d0, d1; upk2(d0, d1, acc2[i][jp]);
            if (mode == 0) {
                int d = col & 31;
                if (col < 512) {
                    int h = (col >> 5) & 7;
                    float* dst = (col < 256) ? g_q : g_k;
                    *(float2*)(dst + (((size_t)bidx*Hh + h)*Nn + n)*HD + d) = make_float2(d0, d1);
                } else {
                    int h = (col - 512) >> 5;
                    *(float2*)(g_v + (((size_t)bidx*Hh + h)*Nn + n)*HD + d) = make_float2(d0, d1);
                }
            } else {
                *(float2*)(out + (size_t)r * 256 + col) =
                    make_float2(d0 + bias[col], d1 + bias[col + 1]);
            }
        }
    }
}

// =====================================================================
// Attention: one CTA per (b,h), 8 warps, QR=8, 2 CTAs/SM.
// QK: FFMA2 paired over adjacent m (K pre-paired d-major in smem) —
// no per-element packing in the hot loop. Scores stay m-paired through
// softmax (exp*(1-g)/sum repacked in place). AV: per-64-m block through
// per-warp sc tile (even/odd split, conflict-free), V pre-paired in
// matching interleaved order. pos weights reconstructed inline with one
// folded constant per query.
// =====================================================================
#define KS2_PITCH 161                       // u64 pitch per d-row
#define KS2_U64   (HD*KS2_PITCH)            // 5152
#define VS2_U64   (160*33)                  // 5280
#define ATTN_F_OFF ((KS2_U64 + VS2_U64)*2)  // float offset of myq region
#define ATTN_SMEM_BYTES ((KS2_U64 + VS2_U64)*8 + (AW*256 + AW*512)*4)  // 108032

__global__ __launch_bounds__(AW*32, 2)
void attn_kernel(const float* __restrict__ Wpos,
                 const float* __restrict__ bpos,
                 const float* __restrict__ gating)
{
    extern __shared__ __align__(16) unsigned long long smu[];
    unsigned long long* ks2 = smu;                 // [d*161 + mp] = (K[2mp][d],K[2mp+1][d])
    unsigned long long* vs2 = smu + KS2_U64;       // [gp*33 + d] = interleaved V pairs
    float* fbase = (float*)(smu + KS2_U64 + VS2_U64);

    int bh = blockIdx.x;               // b*8 + h
    int h  = bh & 7, bidx = bh >> 3;
    int tid = threadIdx.x, wid = tid >> 5, lane = tid & 31;

    const float* kg = g_k + (size_t)bh * Nn * HD;
    const float* vg = g_v + (size_t)bh * Nn * HD;
    const float* qg = g_q + (size_t)bh * Nn * HD;

    // ---- stage K pairs, d-major (lane = d; coalesced LDG) ----
    for (int mp = wid; mp < Nn/2; mp += AW) {
        float f0 = kg[(2*mp)*HD + lane];
        float f1 = kg[(2*mp+1)*HD + lane];
        ks2[lane*KS2_PITCH + mp] = pk2(f0, f1);
    }
    // ---- stage V pairs in the interleaved even/odd consumption order ----
    for (int gp = wid; gp < 160; gp += AW) {
        int tb = gp >> 5, p = gp & 31, u = p >> 1;
        int base = tb*64 + ((u < 8) ? 8*u : 8*(u-8) + 1) + ((p & 1) ? 4 : 0);
        int mA = base, mB = base + 2;
        float fA = (mA < Nn) ? vg[mA*HD + lane] : 0.f;
        float fB = (mB < Nn) ? vg[mB*HD + lane] : 0.f;
        vs2[gp*33 + lane] = pk2(fA, fB);
    }
    __syncthreads();

    float g  = 1.0f / (1.0f + __expf(-gating[h]));
    float w0 = Wpos[h*3+0], w2 = Wpos[h*3+2], bps = bpos[h];
    const float scale = 0.17677669529663687f;   // 1/sqrt(32)
    float* myq  = fbase + wid * 256;            // [d*8 + qq], pre-scaled q
    float* mysc = fbase + AW*256 + wid * 512;   // [qq*64 + j]

    for (int n0 = wid*QR; n0 < Nn; n0 += AW*QR) {
        // stage q (pre-scaled): lane = d
        {
            float qv[QR];
            #pragma unroll
            for (int qq = 0; qq < QR; qq++) {
                int n = n0 + qq; int nc = (n < Nn) ? n : (Nn-1);
                qv[qq] = qg[nc*HD + lane] * scale;
            }
            *(float4*)&myq[lane*8]     = make_float4(qv[0], qv[1], qv[2], qv[3]);
            *(float4*)&myq[lane*8 + 4] = make_float4(qv[4], qv[5], qv[6], qv[7]);
        }
        __syncwarp();

        // ---- QK: acc2[qq][tb] = (score at m=2mp, m=2mp+1), mp=tb*32+lane --
        unsigned long long acc2[QR][5];
        #pragma unroll
        for (int qq = 0; qq < QR; qq++)
            #pragma unroll
            for (int tb = 0; tb < 5; tb++) acc2[qq][tb] = 0ULL;

        #pragma unroll
        for (int d = 0; d < HD; d++) {
            float4 qa = *(const float4*)&myq[d*8];
            float4 qb = *(const float4*)&myq[d*8 + 4];
            unsigned long long qd[QR] = {
                pk2(qa.x,qa.x), pk2(qa.y,qa.y), pk2(qa.z,qa.z), pk2(qa.w,qa.w),
                pk2(qb.x,qb.x), pk2(qb.y,qb.y), pk2(qb.z,qb.z), pk2(qb.w,qb.w) };
            #pragma unroll
            for (int tb = 0; tb < 5; tb++) {
                unsigned long long kp = ks2[d*KS2_PITCH + tb*32 + lane];
                #pragma unroll
                for (int qq = 0; qq < QR; qq++)
                    fma2(acc2[qq][tb], qd[qq], kp);
            }
        }

        // ---- softmax per query; repack exp*(1-g)/sum into acc2 ----
        bool valid[5];
        #pragma unroll
        for (int tb = 0; tb < 5; tb++) valid[tb] = (tb*32 + lane) < (Nn/2);
        float cq[QR];                              // folded pos constant
        #pragma unroll
        for (int qq = 0; qq < QR; qq++) {
            int n = n0 + qq; int nc = (n < Nn) ? n : (Nn-1);
            float v[10], mx = -1e30f;
            #pragma unroll
            for (int tb = 0; tb < 5; tb++) {
                float lo, hi; upk2(lo, hi, acc2[qq][tb]);
                v[2*tb]   = valid[tb] ? lo : -1e30f;
                v[2*tb+1] = valid[tb] ? hi : -1e30f;
                mx = fmaxf(mx, fmaxf(v[2*tb], v[2*tb+1]));
            }
            #pragma unroll
            for (int o = 16; o; o >>= 1) mx = fmaxf(mx, __shfl_xor_sync(0xffffffffu, mx, o));
            float esum = 0.f;
            #pragma unroll
            for (int t = 0; t < 10; t++) { v[t] = __expf(v[t] - mx); esum += v[t]; }
            #pragma unroll
            for (int o = 16; o; o >>= 1) esum += __shfl_xor_sync(0xffffffffu, esum, o);
            float inv = (1.0f - g) / esum;
            #pragma unroll
            for (int tb = 0; tb < 5; tb++)
                acc2[qq][tb] = pk2(v[2*tb] * inv, v[2*tb+1] * inv);
            cq[qq] = (bps - g_posmx[h*Nn + nc]) + __logf(g_posinv[h*Nn + nc]);
        }

        // ---- AV in 64-m blocks through per-warp sc tile ----
        unsigned long long o2[QR];
        #pragma unroll
        for (int qq = 0; qq < QR; qq++) o2[qq] = 0ULL;

        #pragma unroll
        for (int tb = 0; tb < 5; tb++) {
            float fmlo = (float)(tb*64 + 2*lane);
            #pragma unroll
            for (int qq = 0; qq < QR; qq++) {
                float lo, hi; upk2(lo, hi, acc2[qq][tb]);
                float slo = 0.f, shi = 0.f;
                if (valid[tb]) {
                    float fn = (float)(n0 + qq);
                    float d0 = fmlo - fn, d1 = fmlo + 1.0f - fn;
                    slo = lo + __expf(fmaf(w2*d0, d0, fmaf(w0, d0, cq[qq])));
                    shi = hi + __expf(fmaf(w2*d1, d1, fmaf(w0, d1, cq[qq])));
                }
                mysc[qq*64 + lane]      = slo;   // even m section
                mysc[qq*64 + 32 + lane] = shi;   // odd m section
            }
            __syncwarp();
            #pragma unroll 4
            for (int u = 0; u < 16; u++) {
                unsigned long long vpA = vs2[(tb*32 + 2*u    )*33 + lane];
                unsigned long long vpB = vs2[(tb*32 + 2*u + 1)*33 + lane];
                #pragma unroll
                for (int qq = 0; qq < QR; qq++) {
                    ulonglong2 a2 = *(const ulonglong2*)&mysc[qq*64 + 4*u];
                    fma2(o2[qq], a2.x, vpA);
                    fma2(o2[qq], a2.y, vpB);
                }
            }
            __syncwarp();
        }

        #pragma unroll
        for (int qq = 0; qq < QR; qq++) {
            int n = n0 + qq;
            if (n < Nn) {
                float lo, hi; upk2(lo, hi, o2[qq]);
                g_oh[((size_t)bidx*Nn + n)*Cc + h*HD + lane] = lo + hi;
            }
        }
    }
}

// =====================================================================
extern "C" void kernel_launch(void* const* d_in, const int* in_sizes, int n_in,
                              void* d_out, int out_size)
{
    const float* x      = (const float*)d_in[0];
    const float* Wqk    = (const float*)d_in[1];
    const float* Wv     = (const float*)d_in[2];
    const float* Wpos   = (const float*)d_in[3];
    const float* bpos   = (const float*)d_in[4];
    const float* Wproj  = (const float*)d_in[5];
    const float* bproj  = (const float*)d_in[6];
    const float* gating = (const float*)d_in[7];
    float* out = (float*)d_out;

    cudaFuncSetAttribute(attn_kernel, cudaFuncAttributeMaxDynamicSharedMemorySize,
                         ATTN_SMEM_BYTES);

    // 1) positional softmax stats
    pos_kernel<<<(Hh*Nn + 3) / 4, 128>>>(Wpos, bpos, gating);

    // 2) QKV projection: [19200,256] @ [768,256]^T
    dim3 g1(6, ROWS / 128);
    gemm_kernel<<<g1, 256>>>(x, Wqk, Wv, nullptr, nullptr, 0);

    // 3) fused gated attention, one CTA per (b,h)
    attn_kernel<<<BH, AW*32, ATTN_SMEM_BYTES>>>(Wpos, bpos, gating);

    // 4) output projection + bias
    dim3 g2(2, ROWS / 128);
    gemm_kernel<<<g2, 256>>>(nullptr, Wproj, nullptr, bproj, out, 1);
}

// round 11
// speedup vs baseline: 1.0095x; 1.0095x over previous
#include <cuda_runtime.h>
#include <math.h>
#include <stdint.h>

// ---------------- problem constants ----------------
#define Bb 64
#define Nn 300
#define Cc 256
#define Hh 8
#define HD 32
#define BH (Bb*Hh)          // 512
#define ROWS (Bb*Nn)        // 19200
#define QR 8                // queries per warp
#define AW 8                // warps in attention CTA (2 CTAs/SM)

// ---------------- scratch (device globals; no runtime alloc) ----------------
__device__ float g_q[BH * Nn * HD];     // [b,h,n,d]
__device__ float g_k[BH * Nn * HD];
__device__ float g_v[BH * Nn * HD];
__device__ float g_posmx[Hh * Nn];      // per-(h,n) positional logit max
__device__ float g_posinv[Hh * Nn];     // g(h) / sum(exp(logit - max))
__device__ float g_oh[ROWS * Cc];       // attention output, [b,n,h*32+d]

// ---------------- packed f32x2 helpers ----------------
__device__ __forceinline__ unsigned long long pk2(float x, float y) {
    unsigned long long r;
    asm("mov.b64 %0, {%1,%2};" : "=l"(r)
        : "r"(__float_as_uint(x)), "r"(__float_as_uint(y)));
    return r;
}
__device__ __forceinline__ void fma2(unsigned long long& d,
                                     unsigned long long a, unsigned long long b) {
    asm("fma.rn.f32x2 %0, %1, %2, %0;" : "+l"(d) : "l"(a), "l"(b));
}
__device__ __forceinline__ void upk2(float& lo, float& hi, unsigned long long v) {
    uint32_t l, h;
    asm("mov.b64 {%0,%1}, %2;" : "=r"(l), "=r"(h) : "l"(v));
    lo = __uint_as_float(l); hi = __uint_as_float(h);
}

// =====================================================================
// positional softmax stats: logit[h][n][m] = w0*d + w2*d^2 + b, d = m-n.
// =====================================================================
__global__ void pos_kernel(const float* __restrict__ Wpos,
                           const float* __restrict__ bpos,
                           const float* __restrict__ gating)
{
    int row  = blockIdx.x * 4 + (threadIdx.x >> 5);   // h*300 + n
    int lane = threadIdx.x & 31;
    if (row >= Hh * Nn) return;
    int h = row / Nn, n = row % Nn;
    float w0 = Wpos[h*3+0], w2 = Wpos[h*3+2], b = bpos[h];

    float s[10], mx = -1e30f;
    #pragma unroll
    for (int t = 0; t < 10; t++) {
        int m = t*32 + lane;
        float v = -1e30f;
        if (m < Nn) { float d = (float)(m - n); v = fmaf(w2*d, d, fmaf(w0, d, b)); }
        s[t] = v; mx = fmaxf(mx, v);
    }
    #pragma unroll
    for (int o = 16; o; o >>= 1) mx = fmaxf(mx, __shfl_xor_sync(0xffffffffu, mx, o));
    float esum = 0.f;
    #pragma unroll
    for (int t = 0; t < 10; t++) esum += __expf(s[t] - mx);
    #pragma unroll
    for (int o = 16; o; o >>= 1) esum += __shfl_xor_sync(0xffffffffu, esum, o);
    if (lane == 0) {
        float g = 1.0f / (1.0f + __expf(-gating[h]));
        g_posmx[row]  = mx;
        g_posinv[row] = g / esum;
    }
}

// =====================================================================
// GEMM (R6/R9 version, measured 53us proj): out = A[M,256] @ W[N,256]^T
// =====================================================================
#define KT 16
__global__ __launch_bounds__(256, 2)
void gemm_kernel(const float* __restrict__ A,
                 const float* __restrict__ W0,
                 const float* __restrict__ W1,
                 const float* __restrict__ bias,
                 float* __restrict__ out,
                 int mode)
{
    __shared__ __align__(16) float As[2][KT][132];
    __shared__ __align__(16) float Bs[2][KT][132];

    int tid  = threadIdx.x;
    int row0 = blockIdx.y * 128;
    int col0 = blockIdx.x * 128;
    int tx = tid & 15, ty = tid >> 4;

    const float* Ap = (mode == 0) ? A : g_oh;

    int lr = tid >> 1;
    int lk = (tid & 1) * 8;
    const float* arow = Ap + (size_t)(row0 + lr) * 256 + lk;
    int c = col0 + lr;
    const float* wrow;
    if (mode == 0) wrow = (c < 512) ? (W0 + (size_t)c * 256 + lk)
                                    : (W1 + (size_t)(c - 512) * 256 + lk);
    else           wrow = W0 + (size_t)c * 256 + lk;

    unsigned long long acc2[8][4];
    #pragma unroll
    for (int i = 0; i < 8; i++)
        #pragma unroll
        for (int jp = 0; jp < 4; jp++) acc2[i][jp] = 0ULL;

    float4 ra0, ra1, rb0, rb1;
    ra0 = *(const float4*)(arow + 0);
    ra1 = *(const float4*)(arow + 4);
    rb0 = *(const float4*)(wrow + 0);
    rb1 = *(const float4*)(wrow + 4);
    int buf = 0;
    {
        As[0][lk+0][lr]=ra0.x; As[0][lk+1][lr]=ra0.y; As[0][lk+2][lr]=ra0.z; As[0][lk+3][lr]=ra0.w;
        As[0][lk+4][lr]=ra1.x; As[0][lk+5][lr]=ra1.y; As[0][lk+6][lr]=ra1.z; As[0][lk+7][lr]=ra1.w;
        Bs[0][lk+0][lr]=rb0.x; Bs[0][lk+1][lr]=rb0.y; Bs[0][lk+2][lr]=rb0.z; Bs[0][lk+3][lr]=rb0.w;
        Bs[0][lk+4][lr]=rb1.x; Bs[0][lk+5][lr]=rb1.y; Bs[0][lk+6][lr]=rb1.z; Bs[0][lk+7][lr]=rb1.w;
    }
    __syncthreads();

    for (int k0 = 0; k0 < 256; k0 += KT) {
        bool has_next = (k0 + KT) < 256;
        if (has_next) {
            ra0 = *(const float4*)(arow + k0 + KT + 0);
            ra1 = *(const float4*)(arow + k0 + KT + 4);
            rb0 = *(const float4*)(wrow + k0 + KT + 0);
            rb1 = *(const float4*)(wrow + k0 + KT + 4);
        }
        #pragma unroll
        for (int kk = 0; kk < KT; kk++) {
            float4 a0 = *(const float4*)&As[buf][kk][ty*4];
            float4 a1 = *(const float4*)&As[buf][kk][64 + ty*4];
            ulonglong2 bb0 = *(const ulonglong2*)&Bs[buf][kk][tx*4];
            ulonglong2 bb1 = *(const ulonglong2*)&Bs[buf][kk][64 + tx*4];
            unsigned long long bp[4] = {bb0.x, bb0.y, bb1.x, bb1.y};
            float a[8] = {a0.x,a0.y,a0.z,a0.w, a1.x,a1.y,a1.z,a1.w};
            #pragma unroll
            for (int i = 0; i < 8; i++) {
                unsigned long long ap = pk2(a[i], a[i]);
                #pragma unroll
                for (int jp = 0; jp < 4; jp++)
                    fma2(acc2[i][jp], ap, bp[jp]);
            }
        }
        if (has_next) {
            int nb = buf ^ 1;
            As[nb][lk+0][lr]=ra0.x; As[nb][lk+1][lr]=ra0.y; As[nb][lk+2][lr]=ra0.z; As[nb][lk+3][lr]=ra0.w;
            As[nb][lk+4][lr]=ra1.x; As[nb][lk+5][lr]=ra1.y; As[nb][lk+6][lr]=ra1.z; As[nb][lk+7][lr]=ra1.w;
            Bs[nb][lk+0][lr]=rb0.x; Bs[nb][lk+1][lr]=rb0.y; Bs[nb][lk+2][lr]=rb0.z; Bs[nb][lk+3][lr]=rb0.w;
            Bs[nb][lk+4][lr]=rb1.x; Bs[nb][lk+5][lr]=rb1.y; Bs[nb][lk+6][lr]=rb1.z; Bs[nb][lk+7][lr]=rb1.w;
            __syncthreads();
            buf = nb;
        }
    }

    #pragma unroll
    for (int i = 0; i < 8; i++) {
        int r = row0 + ((i < 4) ? (ty*4 + i) : (64 + ty*4 + i - 4));
        int bidx = r / Nn, n = r % Nn;
        #pragma unroll
        for (int jp = 0; jp < 4; jp++) {
            int col = col0 + ((jp < 2) ? (tx*4 + jp*2) : (64 + tx*4 + (jp-2)*2));
            float d0, d1; upk2(d0, d1, acc2[i][jp]);
            if (mode == 0) {
                int d = col & 31;
                if (col < 512) {
                    int h = (col >> 5) & 7;
                    float* dst = (col < 256) ? g_q : g_k;
                    *(float2*)(dst + (((size_t)bidx*Hh + h)*Nn + n)*HD + d) = make_float2(d0, d1);
                } else {
                    int h = (col - 512) >> 5;
                    *(float2*)(g_v + (((size_t)bidx*Hh + h)*Nn + n)*HD + d) = make_float2(d0, d1);
                }
            } else {
                *(float2*)(out + (size_t)r * 256 + col) =
                    make_float2(d0 + bias[col], d1 + bias[col + 1]);
            }
        }
    }
}

// =====================================================================
// Attention: one CTA per (b,h), 8 warps, QR=8, 2 CTAs/SM.
// K pre-paired over adjacent m (d-major): QK does LDS.64 per K pair ->
// half the K wavefronts per query. Scores stay m-paired in regs through
// softmax. AV per 64-m block through per-warp sc tile; V pre-paired
// (m,m+1) in natural order. pos stats stashed in smem (saves regs);
// pos weights recomputed inline exactly as pos_kernel (full accuracy).
// attn = (1-g)*softmax(QK^T*scale) + g*pos  (rows sum to 1 -> no renorm)
// =====================================================================
#define KS2_U64 (HD*150)                    // 4800
#define VS2_U64 (160*HD)                    // 5120
#define MYPC_U64 (AW*QR)                    // 64
#define ATTN_SMEM_BYTES ((KS2_U64 + VS2_U64 + MYPC_U64)*8 + (AW*256 + AW*512)*4)

__global__ __launch_bounds__(AW*32, 2)
void attn_kernel(const float* __restrict__ Wpos,
                 const float* __restrict__ bpos,
                 const float* __restrict__ gating)
{
    extern __shared__ __align__(16) unsigned long long smu[];
    unsigned long long* ks2  = smu;                         // [d*150 + mp]
    unsigned long long* vs2  = smu + KS2_U64;               // [gp*32 + d]
    unsigned long long* mypc = smu + KS2_U64 + VS2_U64;     // [wid*8 + qq]
    float* fbase = (float*)(smu + KS2_U64 + VS2_U64 + MYPC_U64);

    int bh = blockIdx.x;               // b*8 + h
    int h  = bh & 7, bidx = bh >> 3;
    int tid = threadIdx.x, wid = tid >> 5, lane = tid & 31;

    const float* kg = g_k + (size_t)bh * Nn * HD;
    const float* vg = g_v + (size_t)bh * Nn * HD;
    const float* qg = g_q + (size_t)bh * Nn * HD;

    // ---- stage K pairs, d-major (lane = d; coalesced LDG) ----
    for (int mp = wid; mp < 150; mp += AW) {
        float f0 = kg[(2*mp)*HD + lane];
        float f1 = kg[(2*mp+1)*HD + lane];
        ks2[lane*150 + mp] = pk2(f0, f1);
    }
    // ---- stage V pairs (m, m+1), zeros beyond Nn ----
    for (int gp = wid; gp < 160; gp += AW) {
        int mA = 2*gp, mB = 2*gp + 1;
        float fA = (mA < Nn) ? vg[mA*HD + lane] : 0.f;
        float fB = (mB < Nn) ? vg[mB*HD + lane] : 0.f;
        vs2[gp*HD + lane] = pk2(fA, fB);
    }
    __syncthreads();

    float g  = 1.0f / (1.0f + __expf(-gating[h]));
    float w0 = Wpos[h*3+0], w2 = Wpos[h*3+2], bps = bpos[h];
    const float scale = 0.17677669529663687f;   // 1/sqrt(32)
    float* myq  = fbase + wid * 256;            // [d*8 + qq], pre-scaled q
    float* mysc = fbase + AW*256 + wid * 512;   // [qq*64 + j]
    unsigned long long* mypcw = mypc + wid * QR;

    // clamped K-pair indices per block (lanes with mp>=150 are masked later)
    int mpc[5];
    #pragma unroll
    for (int tb = 0; tb < 5; tb++) {
        int mp = tb*32 + lane;
        mpc[tb] = (mp < 150) ? mp : 149;
    }

    for (int n0 = wid*QR; n0 < Nn; n0 += AW*QR) {
        // ---- stage q (pre-scaled), interleaved [d][qq]; lane = d ----
        {
            float qv[QR];
            #pragma unroll
            for (int qq = 0; qq < QR; qq++) {
                int n = n0 + qq; int nc = (n < Nn) ? n : (Nn-1);
                qv[qq] = qg[nc*HD + lane] * scale;
            }
            *(float4*)&myq[lane*8]     = make_float4(qv[0], qv[1], qv[2], qv[3]);
            *(float4*)&myq[lane*8 + 4] = make_float4(qv[4], qv[5], qv[6], qv[7]);
        }
        __syncwarp();

        // ---- QK: acc2[qq][tb] = (score m=2mp, m=2mp+1), mp=tb*32+lane ----
        unsigned long long acc2[QR][5];
        #pragma unroll
        for (int qq = 0; qq < QR; qq++)
            #pragma unroll
            for (int tb = 0; tb < 5; tb++) acc2[qq][tb] = 0ULL;

        #pragma unroll
        for (int d = 0; d < HD; d++) {
            float4 qa = *(const float4*)&myq[d*8];
            float4 qb = *(const float4*)&myq[d*8 + 4];
            unsigned long long q0 = pk2(qa.x, qa.x), q1 = pk2(qa.y, qa.y);
            unsigned long long q2 = pk2(qa.z, qa.z), q3 = pk2(qa.w, qa.w);
            unsigned long long q4 = pk2(qb.x, qb.x), q5 = pk2(qb.y, qb.y);
            unsigned long long q6 = pk2(qb.z, qb.z), q7 = pk2(qb.w, qb.w);
            #pragma unroll
            for (int tb = 0; tb < 5; tb++) {
                unsigned long long kp = ks2[d*150 + mpc[tb]];
                fma2(acc2[0][tb], q0, kp); fma2(acc2[1][tb], q1, kp);
                fma2(acc2[2][tb], q2, kp); fma2(acc2[3][tb], q3, kp);
                fma2(acc2[4][tb], q4, kp); fma2(acc2[5][tb], q5, kp);
                fma2(acc2[6][tb], q6, kp); fma2(acc2[7][tb], q7, kp);
            }
        }

        // ---- softmax per query (in place); stash pos stats in smem ----
        #pragma unroll
        for (int qq = 0; qq < QR; qq++) {
            float vb[10], mx = -1e30f;
            #pragma unroll
            for (int tb = 0; tb < 5; tb++) {
                float lo, hi; upk2(lo, hi, acc2[qq][tb]);
                bool val = (tb*32 + lane) < 150;
                vb[2*tb]   = val ? lo : -1e30f;
                vb[2*tb+1] = val ? hi : -1e30f;
                mx = fmaxf(mx, fmaxf(vb[2*tb], vb[2*tb+1]));
            }
            #pragma unroll
            for (int o = 16; o; o >>= 1) mx = fmaxf(mx, __shfl_xor_sync(0xffffffffu, mx, o));
            float esum = 0.f;
            #pragma unroll
            for (int t = 0; t < 10; t++) { vb[t] = __expf(vb[t] - mx); esum += vb[t]; }
            #pragma unroll
            for (int o = 16; o; o >>= 1) esum += __shfl_xor_sync(0xffffffffu, esum, o);
            float inv = (1.0f - g) / esum;
            #pragma unroll
            for (int tb = 0; tb < 5; tb++)
                acc2[qq][tb] = pk2(vb[2*tb] * inv, vb[2*tb+1] * inv);
            if (lane == 0) {
                int n = n0 + qq; int nc = (n < Nn) ? n : (Nn-1);
                mypcw[qq] = pk2(g_posmx[h*Nn + nc], g_posinv[h*Nn + nc]);
            }
        }
        __syncwarp();

        // ---- AV in 64-m blocks through per-warp sc tile ----
        unsigned long long o2[QR];
        #pragma unroll
        for (int qq = 0; qq < QR; qq++) o2[qq] = 0ULL;

        #pragma unroll
        for (int tb = 0; tb < 5; tb++) {
            bool val = (tb*32 + lane) < 150;
            float fm0 = (float)(tb*64 + 2*lane);
            #pragma unroll
            for (int qq = 0; qq < QR; qq++) {
                float lo, hi; upk2(lo, hi, acc2[qq][tb]);
                float pmxv, pinvv; upk2(pmxv, pinvv, mypcw[qq]);
                float fn = (float)(n0 + qq);
                float d0 = fm0 - fn, d1 = d0 + 1.0f;
                float s0 = 0.f, s1 = 0.f;
                if (val) {
                    float e0 = __expf(fmaf(w2*d0, d0, fmaf(w0, d0, bps)) - pmxv) * pinvv;
                    float e1 = __expf(fmaf(w2*d1, d1, fmaf(w0, d1, bps)) - pmxv) * pinvv;
                    s0 = lo + e0; s1 = hi + e1;
                }
                *(unsigned long long*)&mysc[qq*64 + 2*lane] = pk2(s0, s1);
            }
            __syncwarp();
            #pragma unroll 4
            for (int u = 0; u < 16; u++) {
                unsigned long long vpA = vs2[(tb*32 + 2*u    )*HD + lane];
                unsigned long long vpB = vs2[(tb*32 + 2*u + 1)*HD + lane];
                #pragma unroll
                for (int qq = 0; qq < QR; qq++) {
                    ulonglong2 a2 = *(const ulonglong2*)&mysc[qq*64 + 4*u];
                    fma2(o2[qq], a2.x, vpA);
                    fma2(o2[qq], a2.y, vpB);
                }
            }
            __syncwarp();
        }

        #pragma unroll
        for (int qq = 0; qq < QR; qq++) {
            int n = n0 + qq;
            if (n < Nn) {
                float lo, hi; upk2(lo, hi, o2[qq]);
                g_oh[((size_t)bidx*Nn + n)*Cc + h*HD + lane] = lo + hi;
            }
        }
    }
}

// =====================================================================
extern "C" void kernel_launch(void* const* d_in, const int* in_sizes, int n_in,
                              void* d_out, int out_size)
{
    const float* x      = (const float*)d_in[0];
    const float* Wqk    = (const float*)d_in[1];
    const float* Wv     = (const float*)d_in[2];
    const float* Wpos   = (const float*)d_in[3];
    const float* bpos   = (const float*)d_in[4];
    const float* Wproj  = (const float*)d_in[5];
    const float* bproj  = (const float*)d_in[6];
    const float* gating = (const float*)d_in[7];
    float* out = (float*)d_out;

    cudaFuncSetAttribute(attn_kernel, cudaFuncAttributeMaxDynamicSharedMemorySize,
                         ATTN_SMEM_BYTES);

    // 1) positional softmax stats
    pos_kernel<<<(Hh*Nn + 3) / 4, 128>>>(Wpos, bpos, gating);

    // 2) QKV projection: [19200,256] @ [768,256]^T
    dim3 g1(6, ROWS / 128);
    gemm_kernel<<<g1, 256>>>(x, Wqk, Wv, nullptr, nullptr, 0);

    // 3) fused gated attention, one CTA per (b,h)
    attn_kernel<<<BH, AW*32, ATTN_SMEM_BYTES>>>(Wpos, bpos, gating);

    // 4) output projection + bias
    dim3 g2(2, ROWS / 128);
    gemm_kernel<<<g2, 256>>>(nullptr, Wproj, nullptr, bproj, out, 1);
}

// round 12
// speedup vs baseline: 1.1071x; 1.0967x over previous
#include <cuda_runtime.h>
#include <cuda_bf16.h>
#include <math.h>
#include <stdint.h>

// ---------------- problem constants ----------------
#define Bb 64
#define Nn 300
#define Cc 256
#define Hh 8
#define HD 32
#define BH (Bb*Hh)          // 512
#define ROWS (Bb*Nn)        // 19200
#define QR 4                // queries per warp (attention)
#define AW 8                // warps in attention CTA (2 CTAs/SM)
#define KP 33               // float pitch for K rows (conflict-free)

// ---------------- scratch (device globals; no runtime alloc) ----------------
__device__ float g_q[BH * Nn * HD];     // [b,h,n,d]
__device__ float g_k[BH * Nn * HD];
__device__ float g_v[BH * Nn * HD];
__device__ float g_posmx[Hh * Nn];      // per-(h,n) positional logit max
__device__ float g_posinv[Hh * Nn];     // g(h) / sum(exp(logit - max))
// bf16 hi/lo decompositions for tensor-core GEMMs
__device__ __align__(16) __nv_bfloat16 g_xhi[ROWS * Cc],  g_xlo[ROWS * Cc];
__device__ __align__(16) __nv_bfloat16 g_whi[768 * Cc],   g_wlo[768 * Cc];   // [Wqk;Wv]
__device__ __align__(16) __nv_bfloat16 g_pwhi[Cc * Cc],   g_pwlo[Cc * Cc];   // Wproj
__device__ __align__(16) __nv_bfloat16 g_ohhi[ROWS * Cc], g_ohlo[ROWS * Cc]; // attn out

// ---------------- packed f32x2 helpers (attention) ----------------
__device__ __forceinline__ unsigned long long pk2(float x, float y) {
    unsigned long long r;
    asm("mov.b64 %0, {%1,%2};" : "=l"(r)
        : "r"(__float_as_uint(x)), "r"(__float_as_uint(y)));
    return r;
}
__device__ __forceinline__ void fma2(unsigned long long& d,
                                     unsigned long long a, unsigned long long b) {
    asm("fma.rn.f32x2 %0, %1, %2, %0;" : "+l"(d) : "l"(a), "l"(b));
}
__device__ __forceinline__ void upk2(float& lo, float& hi, unsigned long long v) {
    uint32_t l, h;
    asm("mov.b64 {%0,%1}, %2;" : "=r"(l), "=r"(h) : "l"(v));
    lo = __uint_as_float(l); hi = __uint_as_float(h);
}

// ---------------- mma.sync helper (baseline PTX, sm_80+) ----------------
__device__ __forceinline__ void mma16816(float* c, const uint32_t* a, const uint32_t* b) {
    asm volatile("mma.sync.aligned.m16n8k16.row.col.f32.bf16.bf16.f32 "
        "{%0,%1,%2,%3}, {%4,%5,%6,%7}, {%8,%9}, {%0,%1,%2,%3};"
        : "+f"(c[0]), "+f"(c[1]), "+f"(c[2]), "+f"(c[3])
        : "r"(a[0]), "r"(a[1]), "r"(a[2]), "r"(a[3]), "r"(b[0]), "r"(b[1]));
}

// =====================================================================
// fp32 -> bf16 hi/lo converters (write device globals from device code)
// =====================================================================
__device__ __forceinline__ void cvt_store4(float4 v, __nv_bfloat16* hi, __nv_bfloat16* lo,
                                           size_t e) {
    __nv_bfloat16 h0 = __float2bfloat16(v.x), h1 = __float2bfloat16(v.y);
    __nv_bfloat16 h2 = __float2bfloat16(v.z), h3 = __float2bfloat16(v.w);
    __nv_bfloat16 l0 = __float2bfloat16(v.x - __bfloat162float(h0));
    __nv_bfloat16 l1 = __float2bfloat16(v.y - __bfloat162float(h1));
    __nv_bfloat16 l2 = __float2bfloat16(v.z - __bfloat162float(h2));
    __nv_bfloat16 l3 = __float2bfloat16(v.w - __bfloat162float(h3));
    __nv_bfloat162* hp = (__nv_bfloat162*)(hi + e);
    __nv_bfloat162* lp = (__nv_bfloat162*)(lo + e);
    hp[0] = __halves2bfloat162(h0, h1); hp[1] = __halves2bfloat162(h2, h3);
    lp[0] = __halves2bfloat162(l0, l1); lp[1] = __halves2bfloat162(l2, l3);
}

__global__ void cvt_x_kernel(const float* __restrict__ src, int n4) {
    int i = blockIdx.x * blockDim.x + threadIdx.x;
    if (i >= n4) return;
    cvt_store4(((const float4*)src)[i], g_xhi, g_xlo, (size_t)i * 4);
}

__global__ void cvt_w_kernel(const float* __restrict__ Wqk, const float* __restrict__ Wv,
                             const float* __restrict__ Wproj) {
    int i = blockIdx.x * blockDim.x + threadIdx.x;   // float4 index
    if (i < 49152) {                                  // 768*256/4 combined [Wqk;Wv]
        size_t e = (size_t)i * 4;
        const float* s = (e < 512u*256u) ? (Wqk + e) : (Wv + e - 512u*256u);
        cvt_store4(*(const float4*)s, g_whi, g_wlo, e);
    } else if (i < 49152 + 16384) {                   // 256*256/4 Wproj
        size_t e = (size_t)(i - 49152) * 4;
        cvt_store4(((const float4*)Wproj)[i - 49152], g_pwhi, g_pwlo, e);
    }
}

// =====================================================================
// positional softmax stats: logit[h][n][m] = w0*d + w2*d^2 + b, d = m-n.
// =====================================================================
__global__ void pos_kernel(const float* __restrict__ Wpos,
                           const float* __restrict__ bpos,
                           const float* __restrict__ gating)
{
    int row  = blockIdx.x * 4 + (threadIdx.x >> 5);   // h*300 + n
    int lane = threadIdx.x & 31;
    if (row >= Hh * Nn) return;
    int h = row / Nn, n = row % Nn;
    float w0 = Wpos[h*3+0], w2 = Wpos[h*3+2], b = bpos[h];

    float s[10], mx = -1e30f;
    #pragma unroll
    for (int t = 0; t < 10; t++) {
        int m = t*32 + lane;
        float v = -1e30f;
        if (m < Nn) { float d = (float)(m - n); v = fmaf(w2*d, d, fmaf(w0, d, b)); }
        s[t] = v; mx = fmaxf(mx, v);
    }
    #pragma unroll
    for (int o = 16; o; o >>= 1) mx = fmaxf(mx, __shfl_xor_sync(0xffffffffu, mx, o));
    float esum = 0.f;
    #pragma unroll
    for (int t = 0; t < 10; t++) esum += __expf(s[t] - mx);
    #pragma unroll
    for (int o = 16; o; o >>= 1) esum += __shfl_xor_sync(0xffffffffu, esum, o);
    if (lane == 0) {
        float g = 1.0f / (1.0f + __expf(-gating[h]));
        g_posmx[row]  = mx;
        g_posinv[row] = g / esum;
    }
}

// =====================================================================
// mma.sync GEMM: D[128,128] tile of A[rows,256] @ W[ncols,256]^T
// bf16 3-term split: D = Ahi*Whi + Alo*Whi + Ahi*Wlo (fp32 accum).
// K chunked by 32, static 40KB smem (pad 40), register prefetch, plain
// LDS fragment loads per the documented mma layout. ALL global scratch
// referenced in device code (R4/R5 passed __device__ symbols as host
// args -> GPU read the host-side shadow via ATS -> silent zeros).
// mode 0: A=g_xhi/lo, W=g_whi/lo, scatter into g_q/g_k/g_v.
// mode 1: A=g_ohhi/lo, W=g_pwhi/lo, out = D + bias.
// =====================================================================
#define PAD 40   // row pitch in bf16 elems (80B)

__global__ __launch_bounds__(256, 2)
void tc_gemm(const float* __restrict__ bias, float* __restrict__ out, int mode)
{
    __shared__ __align__(16) __nv_bfloat16 sm[4][128 * PAD];   // Ahi,Alo,Bhi,Blo

    int tid = threadIdx.x, wid = tid >> 5, lane = tid & 31;
    int row0 = blockIdx.y * 128;
    int col0 = blockIdx.x * 128;
    int warpM = wid & 1;           // 2 x 64 rows
    int warpN = wid >> 1;          // 4 x 32 cols
    int g  = lane >> 2;            // fragment row group 0..7
    int tg = lane & 3;             // fragment k group

    const __nv_bfloat16* srcs[4];
    if (mode == 0) {
        srcs[0] = g_xhi + (size_t)row0 * 256;
        srcs[1] = g_xlo + (size_t)row0 * 256;
        srcs[2] = g_whi + (size_t)col0 * 256;
        srcs[3] = g_wlo + (size_t)col0 * 256;
    } else {
        srcs[0] = g_ohhi + (size_t)row0 * 256;
        srcs[1] = g_ohlo + (size_t)row0 * 256;
        srcs[2] = g_pwhi + (size_t)col0 * 256;
        srcs[3] = g_pwlo + (size_t)col0 * 256;
    }

    int lr_half = tid >> 2;        // 0..63
    int lu = tid & 3;              // 16B unit within 32-elem chunk

    float acc[4][4][4];
    #pragma unroll
    for (int mt = 0; mt < 4; mt++)
        #pragma unroll
        for (int nt = 0; nt < 4; nt++)
            #pragma unroll
            for (int f = 0; f < 4; f++) acc[mt][nt][f] = 0.f;

    uint4 rv[8];
    #pragma unroll
    for (int i = 0; i < 8; i++) {
        int tile = i >> 1;
        int r = (i & 1) * 64 + lr_half;
        rv[i] = *(const uint4*)(srcs[tile] + (size_t)r * 256 + lu * 8);
    }
    #pragma unroll
    for (int i = 0; i < 8; i++) {
        int tile = i >> 1;
        int r = (i & 1) * 64 + lr_half;
        *(uint4*)((char*)sm[tile] + r * (PAD*2) + lu * 16) = rv[i];
    }

    for (int kc = 0; kc < 8; kc++) {
        __syncthreads();
        if (kc < 7) {
            int k0 = (kc + 1) * 32;
            #pragma unroll
            for (int i = 0; i < 8; i++) {
                int tile = i >> 1;
                int r = (i & 1) * 64 + lr_half;
                rv[i] = *(const uint4*)(srcs[tile] + (size_t)r * 256 + k0 + lu * 8);
            }
        }

        #pragma unroll
        for (int kg = 0; kg < 2; kg++) {
            int kb = kg * 16 + tg * 2;        // element offset in row
            uint32_t Ah[4][4], Al[4][4];
            #pragma unroll
            for (int mt = 0; mt < 4; mt++) {
                const char* pa = (const char*)sm[0] +
                                 (warpM*64 + mt*16 + g) * (PAD*2) + kb * 2;
                const char* pl = (const char*)sm[1] +
                                 (warpM*64 + mt*16 + g) * (PAD*2) + kb * 2;
                Ah[mt][0] = *(const uint32_t*)(pa);
                Ah[mt][1] = *(const uint32_t*)(pa + 8 * (PAD*2));
                Ah[mt][2] = *(const uint32_t*)(pa + 16);
                Ah[mt][3] = *(const uint32_t*)(pa + 8 * (PAD*2) + 16);
                Al[mt][0] = *(const uint32_t*)(pl);
                Al[mt][1] = *(const uint32_t*)(pl + 8 * (PAD*2));
                Al[mt][2] = *(const uint32_t*)(pl + 16);
                Al[mt][3] = *(const uint32_t*)(pl + 8 * (PAD*2) + 16);
            }
            uint32_t Bh[4][2], Bl[4][2];
            #pragma unroll
            for (int nt = 0; nt < 4; nt++) {
                const char* pb = (const char*)sm[2] +
                                 (warpN*32 + nt*8 + g) * (PAD*2) + kb * 2;
                const char* pbl = (const char*)sm[3] +
                                 (warpN*32 + nt*8 + g) * (PAD*2) + kb * 2;
                Bh[nt][0] = *(const uint32_t*)(pb);
                Bh[nt][1] = *(const uint32_t*)(pb + 16);
                Bl[nt][0] = *(const uint32_t*)(pbl);
                Bl[nt][1] = *(const uint32_t*)(pbl + 16);
            }
            #pragma unroll
            for (int mt = 0; mt < 4; mt++)
                #pragma unroll
                for (int nt = 0; nt < 4; nt++) {
                    mma16816(acc[mt][nt], Ah[mt], Bh[nt]);
                    mma16816(acc[mt][nt], Al[mt], Bh[nt]);
                    mma16816(acc[mt][nt], Ah[mt], Bl[nt]);
                }
        }

        if (kc < 7) {
            __syncthreads();
            #pragma unroll
            for (int i = 0; i < 8; i++) {
                int tile = i >> 1;
                int r = (i & 1) * 64 + lr_half;
                *(uint4*)((char*)sm[tile] + r * (PAD*2) + lu * 16) = rv[i];
            }
        }
    }

    // ---------------- epilogue ----------------
    int sec = col0 >> 8;                                  // mode0: 0=q 1=k 2=v
    int h   = ((col0 & 255) >> 5) + warpN;                // one head per warp
    #pragma unroll
    for (int mt = 0; mt < 4; mt++) {
        #pragma unroll
        for (int rr = 0; rr < 2; rr++) {
            int r = row0 + warpM*64 + mt*16 + (lane >> 2) + rr*8;
            int bidx = r / Nn, n = r % Nn;
            #pragma unroll
            for (int nt = 0; nt < 4; nt++) {
                int col = col0 + warpN*32 + nt*8 + (lane & 3)*2;
                float d0 = acc[mt][nt][rr*2 + 0];
                float d1 = acc[mt][nt][rr*2 + 1];
                if (mode == 0) {
                    float* basep = (sec == 0) ? g_q : (sec == 1) ? g_k : g_v;
                    int d = col & 31;
                    *(float2*)(basep + (((size_t)bidx*Hh + h)*Nn + n)*HD + d) =
                        make_float2(d0, d1);
                } else {
                    *(float2*)(out + (size_t)r * 256 + col) =
                        make_float2(d0 + bias[col], d1 + bias[col + 1]);
                }
            }
        }
    }
}

// =====================================================================
// Attention (R9 measured-best): one CTA per (b,h), 8 warps, QR=4,
// 2 CTAs/SM. AV in 32-m blocks through 512B/warp sc tile; LDS.128 quad
// score broadcasts; pos-mix fused at block write. Output stored as
// bf16 hi/lo for the tensor-core projection.
// =====================================================================
#define SM_U64_VS2 ((Nn/2)*32)                 // 4800 u64
#define SM_F_KS    (Nn*KP)                     // 9900 f
#define ATTN_SMEM_BYTES (SM_U64_VS2*8 + (SM_F_KS + AW*32*QR + AW*QR*32)*4)

__global__ __launch_bounds__(AW*32, 2)
void attn_kernel(const float* __restrict__ Wpos,
                 const float* __restrict__ bpos,
                 const float* __restrict__ gating)
{
    extern __shared__ __align__(16) unsigned long long smu[];
    unsigned long long* vs2 = smu;                         // [(m/2)*32+d] = (V[m],V[m+1])
    float* ks  = (float*)(smu + SM_U64_VS2);               // [m*KP + d]
    float* qs  = ks + SM_F_KS;                             // [wid][d*QR+qq]
    float* scb = qs + AW*32*QR;                            // [wid][qq*32+j]

    int bh = blockIdx.x;               // b*8 + h
    int h  = bh & 7, bidx = bh >> 3;
    int tid = threadIdx.x, wid = tid >> 5, lane = tid & 31;

    const float* kg = g_k + (size_t)bh * Nn * HD;
    const float* vg = g_v + (size_t)bh * Nn * HD;
    const float* qg = g_q + (size_t)bh * Nn * HD;

    for (int i = tid; i < Nn * 8; i += AW*32) {
        int m = i >> 3, d = (i & 7) * 4;
        float4 kv4 = *(const float4*)(kg + m*HD + d);
        ks[m*KP + d + 0] = kv4.x; ks[m*KP + d + 1] = kv4.y;
        ks[m*KP + d + 2] = kv4.z; ks[m*KP + d + 3] = kv4.w;
    }
    for (int i = tid; i < (Nn/2) * 8; i += AW*32) {
        int mp = i >> 3, d = (i & 7) * 4;
        float4 va = *(const float4*)(vg + (2*mp)*HD + d);
        float4 vb = *(const float4*)(vg + (2*mp+1)*HD + d);
        vs2[mp*32 + d + 0] = pk2(va.x, vb.x);
        vs2[mp*32 + d + 1] = pk2(va.y, vb.y);
        vs2[mp*32 + d + 2] = pk2(va.z, vb.z);
        vs2[mp*32 + d + 3] = pk2(va.w, vb.w);
    }
    __syncthreads();

    float g  = 1.0f / (1.0f + __expf(-gating[h]));
    float w0 = Wpos[h*3+0], w2 = Wpos[h*3+2], bps = bpos[h];
    const float scale = 0.17677669529663687f;   // 1/sqrt(32)
    float* myq  = qs  + wid * (32*QR);
    float* mysc = scb + wid * (QR*32);

    for (int n0 = wid*QR; n0 < Nn; n0 += AW*QR) {
        {
            float q0 = qg[(n0+0)*HD + lane];
            float q1 = qg[(n0+1)*HD + lane];
            float q2 = qg[(n0+2)*HD + lane];
            float q3 = qg[(n0+3)*HD + lane];
            *(float4*)&myq[lane*QR] = make_float4(q0, q1, q2, q3);
        }
        __syncwarp();

        unsigned long long acc2[2][10];
        #pragma unroll
        for (int p = 0; p < 2; p++)
            #pragma unroll
            for (int t = 0; t < 10; t++) acc2[p][t] = 0ULL;

        #pragma unroll
        for (int d = 0; d < HD; d++) {
            ulonglong2 qp = *(const ulonglong2*)&myq[d*QR];   // (q0,q1),(q2,q3)
            #pragma unroll
            for (int t = 0; t < 10; t++) {
                float kv = ks[(t*32 + lane)*KP + d];
                unsigned long long kp = pk2(kv, kv);
                fma2(acc2[0][t], qp.x, kp);
                fma2(acc2[1][t], qp.y, kp);
            }
        }

        float s[QR][10], inv[QR], pmx[QR], pw[QR];
        #pragma unroll
        for (int qq = 0; qq < QR; qq++) {
            int n = n0 + qq;
            float mx = -1e30f;
            #pragma unroll
            for (int t = 0; t < 10; t++) {
                float lo, hi; upk2(lo, hi, acc2[qq >> 1][t]);
                float v = (qq & 1) ? hi : lo;
                int m = t*32 + lane;
                v = (m < Nn) ? v * scale : -1e30f;
                s[qq][t] = v; mx = fmaxf(mx, v);
            }
            #pragma unroll
            for (int o = 16; o; o >>= 1) mx = fmaxf(mx, __shfl_xor_sync(0xffffffffu, mx, o));
            float esum = 0.f;
            #pragma unroll
            for (int t = 0; t < 10; t++) { s[qq][t] = __expf(s[qq][t] - mx); esum += s[qq][t]; }
            #pragma unroll
            for (int o = 16; o; o >>= 1) esum += __shfl_xor_sync(0xffffffffu, esum, o);
            inv[qq] = (1.0f - g) / esum;
            pmx[qq] = g_posmx[h*Nn + n];
            pw[qq]  = g_posinv[h*Nn + n];
        }

        unsigned long long o2[QR];
        #pragma unroll
        for (int qq = 0; qq < QR; qq++) o2[qq] = 0ULL;

        #pragma unroll
        for (int t = 0; t < 10; t++) {
            int m = t*32 + lane;
            float fm = (float)m;
            #pragma unroll
            for (int qq = 0; qq < QR; qq++) {
                float av = 0.f;
                if (m < Nn) {
                    float dd = fm - (float)(n0 + qq);
                    float pe = __expf(fmaf(w2*dd, dd, fmaf(w0, dd, bps)) - pmx[qq]) * pw[qq];
                    av = fmaf(s[qq][t], inv[qq], pe);
                }
                mysc[qq*32 + lane] = av;
            }
            __syncwarp();
            int j4max = (t < 9) ? 8 : 3;       // block 9 covers m=288..299 (12 m)
            for (int j4 = 0; j4 < j4max; j4++) {
                unsigned long long vp0 = vs2[(t*16 + 2*j4 + 0)*32 + lane];
                unsigned long long vp1 = vs2[(t*16 + 2*j4 + 1)*32 + lane];
                #pragma unroll
                for (int qq = 0; qq < QR; qq++) {
                    ulonglong2 a4 = *(const ulonglong2*)&mysc[qq*32 + j4*4];
                    fma2(o2[qq], a4.x, vp0);
                    fma2(o2[qq], a4.y, vp1);
                }
            }
            __syncwarp();
        }

        #pragma unroll
        for (int qq = 0; qq < QR; qq++) {
            float lo, hi; upk2(lo, hi, o2[qq]);
            float val = lo + hi;
            __nv_bfloat16 hb = __float2bfloat16(val);
            __nv_bfloat16 lb = __float2bfloat16(val - __bfloat162float(hb));
            size_t idx = ((size_t)bidx*Nn + (n0+qq))*Cc + h*HD + lane;
            g_ohhi[idx] = hb;
            g_ohlo[idx] = lb;
        }
    }
}

// =====================================================================
extern "C" void kernel_launch(void* const* d_in, const int* in_sizes, int n_in,
                              void* d_out, int out_size)
{
    const float* x      = (const float*)d_in[0];
    const float* Wqk    = (const float*)d_in[1];
    const float* Wv     = (const float*)d_in[2];
    const float* Wpos   = (const float*)d_in[3];
    const float* bpos   = (const float*)d_in[4];
    const float* Wproj  = (const float*)d_in[5];
    const float* bproj  = (const float*)d_in[6];
    const float* gating = (const float*)d_in[7];
    float* out = (float*)d_out;

    cudaFuncSetAttribute(attn_kernel, cudaFuncAttributeMaxDynamicSharedMemorySize,
                         ATTN_SMEM_BYTES);

    // 0) bf16 hi/lo conversions (device-side writes to device globals)
    int n4x = ROWS * Cc / 4;
    cvt_x_kernel<<<(n4x + 255) / 256, 256>>>(x, n4x);
    cvt_w_kernel<<<(49152 + 16384 + 255) / 256, 256>>>(Wqk, Wv, Wproj);

    // 1) positional softmax stats
    pos_kernel<<<(Hh*Nn + 3) / 4, 128>>>(Wpos, bpos, gating);

    // 2) QKV projection on tensor cores: [19200,256] @ [768,256]^T
    dim3 g1(6, ROWS / 128);
    tc_gemm<<<g1, 256>>>(nullptr, nullptr, 0);

    // 3) fused gated attention, one CTA per (b,h)
    attn_kernel<<<BH, AW*32, ATTN_SMEM_BYTES>>>(Wpos, bpos, gating);

    // 4) output projection on tensor cores + bias
    dim3 g2(2, ROWS / 128);
    tc_gemm<<<g2, 256>>>(bproj, out, 1);
}